// round 1
// baseline (speedup 1.0000x reference)
#include <cuda_runtime.h>

// Problem dims
#define NTOK 8192          // B*T = 4*2048
#define D_   1024
#define H_   2048
#define E_   8
#define KBIG (E_*H_)       // 16384

// GEMM tiling
#define BM 128
#define BN 128
#define BK 16

// Scratch (device globals: allocation-free kernel_launch)
__device__ float g_gate[NTOK * E_];
__device__ float g_hs[(size_t)NTOK * KBIG];   // gate-scaled relu hidden, [NTOK][E*H]

// ---------------------------------------------------------------------------
// Kernel 1: gate = softmax(x @ Wg + bg).  One warp per token.
// ---------------------------------------------------------------------------
__global__ void gate_kernel(const float* __restrict__ x,
                            const float* __restrict__ Wg,   // [D, E]
                            const float* __restrict__ bg)   // [E]
{
    int gwarp = (blockIdx.x * blockDim.x + threadIdx.x) >> 5;
    int lane  = threadIdx.x & 31;
    if (gwarp >= NTOK) return;

    const float* xr = x + (size_t)gwarp * D_;
    float acc[E_];
#pragma unroll
    for (int e = 0; e < E_; e++) acc[e] = 0.0f;

    for (int k = lane; k < D_; k += 32) {
        float xv = xr[k];
        float4 w0 = *(const float4*)(Wg + k * E_);
        float4 w1 = *(const float4*)(Wg + k * E_ + 4);
        acc[0] = fmaf(xv, w0.x, acc[0]);
        acc[1] = fmaf(xv, w0.y, acc[1]);
        acc[2] = fmaf(xv, w0.z, acc[2]);
        acc[3] = fmaf(xv, w0.w, acc[3]);
        acc[4] = fmaf(xv, w1.x, acc[4]);
        acc[5] = fmaf(xv, w1.y, acc[5]);
        acc[6] = fmaf(xv, w1.z, acc[6]);
        acc[7] = fmaf(xv, w1.w, acc[7]);
    }
#pragma unroll
    for (int e = 0; e < E_; e++) {
#pragma unroll
        for (int off = 16; off; off >>= 1)
            acc[e] += __shfl_xor_sync(0xFFFFFFFFu, acc[e], off);
    }
    if (lane == 0) {
        float m = -1e30f;
#pragma unroll
        for (int e = 0; e < E_; e++) { acc[e] += bg[e]; m = fmaxf(m, acc[e]); }
        float s = 0.0f;
#pragma unroll
        for (int e = 0; e < E_; e++) { acc[e] = __expf(acc[e] - m); s += acc[e]; }
        float inv = 1.0f / s;
#pragma unroll
        for (int e = 0; e < E_; e++) g_gate[gwarp * E_ + e] = acc[e] * inv;
    }
}

// ---------------------------------------------------------------------------
// Kernel 2: hs[n][e*H+h] = relu(x[n,:] @ W1[e,:,h] + b1[e,h]) * gate[n,e]
// Classic 128x128x16 tile, 256 threads, 8x8 micro-tile (split 4+4 @ +64).
// ---------------------------------------------------------------------------
__global__ __launch_bounds__(256, 2)
void gemm1_kernel(const float* __restrict__ x,    // [NTOK, D]
                  const float* __restrict__ W1,   // [E, D, H]
                  const float* __restrict__ b1)   // [E, H]
{
    __shared__ float As[BK][BM + 4];   // +4 pad keeps 16B alignment, cuts write conflicts
    __shared__ float Bs[BK][BN];

    int ht = blockIdx.x;           // H tile
    int nt = blockIdx.y;           // token tile
    int e  = blockIdx.z;           // expert
    int n0 = nt * BM, h0 = ht * BN;
    const float* Bp = W1 + (size_t)e * D_ * H_;   // [D, H] row-major

    int tid = threadIdx.x;
    int tx = tid & 15, ty = tid >> 4;

    float acc[8][8];
#pragma unroll
    for (int i = 0; i < 8; i++)
#pragma unroll
        for (int j = 0; j < 8; j++) acc[i][j] = 0.0f;

    for (int k0 = 0; k0 < D_; k0 += BK) {
        // A tile: 128 rows x 16 k, stored transposed As[k][m]
#pragma unroll
        for (int i = 0; i < 2; i++) {
            int f4 = tid + i * 256;            // 0..511
            int m  = f4 >> 2;
            int c4 = f4 & 3;
            float4 v = *(const float4*)(x + (size_t)(n0 + m) * D_ + k0 + c4 * 4);
            As[c4 * 4 + 0][m] = v.x;
            As[c4 * 4 + 1][m] = v.y;
            As[c4 * 4 + 2][m] = v.z;
            As[c4 * 4 + 3][m] = v.w;
        }
        // B tile: 16 k-rows x 128 h
#pragma unroll
        for (int i = 0; i < 2; i++) {
            int f4 = tid + i * 256;
            int kr = f4 >> 5;                  // 32 float4 per row
            int c4 = f4 & 31;
            *(float4*)&Bs[kr][c4 * 4] =
                *(const float4*)(Bp + (size_t)(k0 + kr) * H_ + h0 + c4 * 4);
        }
        __syncthreads();
#pragma unroll
        for (int kk = 0; kk < BK; kk++) {
            float a[8], b[8];
            *(float4*)&a[0] = *(float4*)&As[kk][ty * 4];
            *(float4*)&a[4] = *(float4*)&As[kk][64 + ty * 4];
            *(float4*)&b[0] = *(float4*)&Bs[kk][tx * 4];
            *(float4*)&b[4] = *(float4*)&Bs[kk][64 + tx * 4];
#pragma unroll
            for (int i = 0; i < 8; i++)
#pragma unroll
                for (int j = 0; j < 8; j++)
                    acc[i][j] = fmaf(a[i], b[j], acc[i][j]);
        }
        __syncthreads();
    }

    // epilogue: +b1, relu, *gate, store to g_hs
#pragma unroll
    for (int i = 0; i < 8; i++) {
        int n = n0 + ((i < 4) ? (ty * 4 + i) : (64 + ty * 4 + i - 4));
        float g = g_gate[n * E_ + e];
        float* dst = g_hs + (size_t)n * KBIG + (size_t)e * H_;
#pragma unroll
        for (int jg = 0; jg < 2; jg++) {
            int hb = h0 + jg * 64 + tx * 4;
            const float* bb = b1 + (size_t)e * H_ + hb;
            float4 v;
            v.x = fmaxf(acc[i][jg * 4 + 0] + bb[0], 0.0f) * g;
            v.y = fmaxf(acc[i][jg * 4 + 1] + bb[1], 0.0f) * g;
            v.z = fmaxf(acc[i][jg * 4 + 2] + bb[2], 0.0f) * g;
            v.w = fmaxf(acc[i][jg * 4 + 3] + bb[3], 0.0f) * g;
            *(float4*)(dst + hb) = v;
        }
    }
}

// ---------------------------------------------------------------------------
// Kernel 3: out[n][d] = hs[n,:] @ W2flat[:,d] + sum_e gate[n,e]*b2[e,d]
// W2 is [E,H,D] == [KBIG, D] row-major already. K = 16384.
// ---------------------------------------------------------------------------
__global__ __launch_bounds__(256, 2)
void gemm2_kernel(const float* __restrict__ W2,   // [KBIG, D]
                  const float* __restrict__ b2,   // [E, D]
                  float* __restrict__ out)        // [NTOK, D]
{
    __shared__ float As[BK][BM + 4];
    __shared__ float Bs[BK][BN];

    int dt = blockIdx.x;           // D tile
    int nt = blockIdx.y;           // token tile
    int n0 = nt * BM, d0 = dt * BN;

    int tid = threadIdx.x;
    int tx = tid & 15, ty = tid >> 4;

    float acc[8][8];
#pragma unroll
    for (int i = 0; i < 8; i++)
#pragma unroll
        for (int j = 0; j < 8; j++) acc[i][j] = 0.0f;

    for (int k0 = 0; k0 < KBIG; k0 += BK) {
#pragma unroll
        for (int i = 0; i < 2; i++) {
            int f4 = tid + i * 256;
            int m  = f4 >> 2;
            int c4 = f4 & 3;
            float4 v = *(const float4*)(g_hs + (size_t)(n0 + m) * KBIG + k0 + c4 * 4);
            As[c4 * 4 + 0][m] = v.x;
            As[c4 * 4 + 1][m] = v.y;
            As[c4 * 4 + 2][m] = v.z;
            As[c4 * 4 + 3][m] = v.w;
        }
#pragma unroll
        for (int i = 0; i < 2; i++) {
            int f4 = tid + i * 256;
            int kr = f4 >> 5;
            int c4 = f4 & 31;
            *(float4*)&Bs[kr][c4 * 4] =
                *(const float4*)(W2 + (size_t)(k0 + kr) * D_ + d0 + c4 * 4);
        }
        __syncthreads();
#pragma unroll
        for (int kk = 0; kk < BK; kk++) {
            float a[8], b[8];
            *(float4*)&a[0] = *(float4*)&As[kk][ty * 4];
            *(float4*)&a[4] = *(float4*)&As[kk][64 + ty * 4];
            *(float4*)&b[0] = *(float4*)&Bs[kk][tx * 4];
            *(float4*)&b[4] = *(float4*)&Bs[kk][64 + tx * 4];
#pragma unroll
            for (int i = 0; i < 8; i++)
#pragma unroll
                for (int j = 0; j < 8; j++)
                    acc[i][j] = fmaf(a[i], b[j], acc[i][j]);
        }
        __syncthreads();
    }

    // bias: acc[i][j] += sum_e gate[n_i,e] * b2[e, d_j]
#pragma unroll
    for (int e = 0; e < E_; e++) {
        float bv[8];
        *(float4*)&bv[0] = *(const float4*)(b2 + (size_t)e * D_ + d0 + tx * 4);
        *(float4*)&bv[4] = *(const float4*)(b2 + (size_t)e * D_ + d0 + 64 + tx * 4);
#pragma unroll
        for (int i = 0; i < 8; i++) {
            int n = n0 + ((i < 4) ? (ty * 4 + i) : (64 + ty * 4 + i - 4));
            float gi = g_gate[n * E_ + e];
#pragma unroll
            for (int j = 0; j < 8; j++)
                acc[i][j] = fmaf(gi, bv[j], acc[i][j]);
        }
    }

    // store
#pragma unroll
    for (int i = 0; i < 8; i++) {
        int n = n0 + ((i < 4) ? (ty * 4 + i) : (64 + ty * 4 + i - 4));
        float* dst = out + (size_t)n * D_;
#pragma unroll
        for (int jg = 0; jg < 2; jg++) {
            int d = d0 + jg * 64 + tx * 4;
            float4 v;
            v.x = acc[i][jg * 4 + 0];
            v.y = acc[i][jg * 4 + 1];
            v.z = acc[i][jg * 4 + 2];
            v.w = acc[i][jg * 4 + 3];
            *(float4*)(dst + d) = v;
        }
    }
}

// ---------------------------------------------------------------------------
extern "C" void kernel_launch(void* const* d_in, const int* in_sizes, int n_in,
                              void* d_out, int out_size)
{
    const float* x  = (const float*)d_in[0];
    const float* Wg = (const float*)d_in[1];
    const float* bg = (const float*)d_in[2];
    const float* W1 = (const float*)d_in[3];
    const float* b1 = (const float*)d_in[4];
    const float* W2 = (const float*)d_in[5];
    const float* b2 = (const float*)d_in[6];
    float* out = (float*)d_out;

    // 1) gating: 8192 warps
    gate_kernel<<<NTOK * 32 / 256, 256>>>(x, Wg, bg);

    // 2) hidden: grid (H tiles, token tiles, experts)
    dim3 g1(H_ / BN, NTOK / BM, E_);
    gemm1_kernel<<<g1, 256>>>(x, W1, b1);

    // 3) output: single big GEMM over K = E*H
    dim3 g2(D_ / BN, NTOK / BM);
    gemm2_kernel<<<g2, 256>>>(W2, b2, out);
}

// round 3
// speedup vs baseline: 6.7103x; 6.7103x over previous
#include <cuda_runtime.h>
#include <cuda_fp16.h>
#include <stdint.h>

#define NTOK 8192
#define D_   1024
#define H_   2048
#define E_   8
#define KBIG (E_*H_)

#define BM 128
#define BN 128
#define BKH 32                 // halves of K per stage
#define RS 40                  // smem row stride in halves (80B): conflict-free ldmatrix
#define STAGE_H   (128*RS)     // halves per operand per stage
#define OPB       (STAGE_H*2)  // 10240 bytes per operand
#define STAGE_BYTES (2*OPB)    // 20480
#define NSTAGE 4
#define SMEM_BYTES (NSTAGE*STAGE_BYTES)   // 81920

// ------------------ scratch ------------------
__device__ float g_gate[NTOK*E_];
__device__ __half g_x16[(size_t)NTOK*D_];
__device__ __half g_w1t16[(size_t)E_*H_*D_];   // [E][H][D]
__device__ __half g_w2t16[(size_t)D_*KBIG];    // [D][KBIG]
__device__ __half g_hs16[(size_t)NTOK*KBIG];   // [NTOK][KBIG]

// ------------------ PTX helpers ------------------
__device__ __forceinline__ uint32_t smem_u32(const void* p){
    uint32_t a;
    asm("{ .reg .u64 t; cvta.to.shared.u64 t, %1; cvt.u32.u64 %0, t; }" : "=r"(a) : "l"(p));
    return a;
}
__device__ __forceinline__ void cpa(uint32_t dst, const void* src){
    asm volatile("cp.async.cg.shared.global [%0], [%1], 16;" :: "r"(dst), "l"(src));
}
__device__ __forceinline__ void ldsm4(uint32_t* r, uint32_t addr){
    asm volatile("ldmatrix.sync.aligned.m8n8.x4.shared.b16 {%0,%1,%2,%3}, [%4];"
        : "=r"(r[0]), "=r"(r[1]), "=r"(r[2]), "=r"(r[3]) : "r"(addr));
}
__device__ __forceinline__ void mma16816(float* c, const uint32_t* a, const uint32_t* b){
    asm volatile("mma.sync.aligned.m16n8k16.row.col.f32.f16.f16.f32 "
        "{%0,%1,%2,%3}, {%4,%5,%6,%7}, {%8,%9}, {%0,%1,%2,%3};"
        : "+f"(c[0]), "+f"(c[1]), "+f"(c[2]), "+f"(c[3])
        : "r"(a[0]), "r"(a[1]), "r"(a[2]), "r"(a[3]), "r"(b[0]), "r"(b[1]));
}

// ------------------ gate = softmax(x@Wg + bg) ------------------
__global__ void gate_kernel(const float* __restrict__ x, const float* __restrict__ Wg,
                            const float* __restrict__ bg){
    int gw = (blockIdx.x*blockDim.x + threadIdx.x) >> 5;
    int lane = threadIdx.x & 31;
    if (gw >= NTOK) return;
    const float* xr = x + (size_t)gw * D_;
    float acc[E_];
#pragma unroll
    for (int e=0;e<E_;e++) acc[e]=0.f;
    for (int k=lane;k<D_;k+=32){
        float xv = xr[k];
        float4 w0 = *(const float4*)(Wg + k*E_);
        float4 w1 = *(const float4*)(Wg + k*E_ + 4);
        acc[0]=fmaf(xv,w0.x,acc[0]); acc[1]=fmaf(xv,w0.y,acc[1]);
        acc[2]=fmaf(xv,w0.z,acc[2]); acc[3]=fmaf(xv,w0.w,acc[3]);
        acc[4]=fmaf(xv,w1.x,acc[4]); acc[5]=fmaf(xv,w1.y,acc[5]);
        acc[6]=fmaf(xv,w1.z,acc[6]); acc[7]=fmaf(xv,w1.w,acc[7]);
    }
#pragma unroll
    for (int e=0;e<E_;e++)
#pragma unroll
        for (int o=16;o;o>>=1) acc[e] += __shfl_xor_sync(0xFFFFFFFFu, acc[e], o);
    if (lane==0){
        float m=-1e30f;
#pragma unroll
        for (int e=0;e<E_;e++){ acc[e]+=bg[e]; m=fmaxf(m,acc[e]); }
        float s=0.f;
#pragma unroll
        for (int e=0;e<E_;e++){ acc[e]=__expf(acc[e]-m); s+=acc[e]; }
        float inv=1.f/s;
#pragma unroll
        for (int e=0;e<E_;e++) g_gate[gw*E_+e]=acc[e]*inv;
    }
}

// ------------------ converts ------------------
__global__ void cvt_x_kernel(const float* __restrict__ x){
    size_t i = ((size_t)blockIdx.x*256 + threadIdx.x) * 4;
    float4 v = *(const float4*)(x + i);
    __half2 a = __halves2half2(__float2half_rn(v.x), __float2half_rn(v.y));
    __half2 b = __halves2half2(__float2half_rn(v.z), __float2half_rn(v.w));
    *(__half2*)(g_x16 + i)     = a;
    *(__half2*)(g_x16 + i + 2) = b;
}

__global__ void cvt_w1_kernel(const float* __restrict__ W1){   // [E,D,H] -> [E,H,D] fp16
    __shared__ float t[32][33];
    int e = blockIdx.z;
    int h0 = blockIdx.x*32, d0 = blockIdx.y*32;
    int c = threadIdx.x, r0 = threadIdx.y;
    const float* src = W1 + (size_t)e*D_*H_;
#pragma unroll
    for (int i=0;i<4;i++){ int r=r0+8*i; t[r][c] = src[(size_t)(d0+r)*H_ + h0 + c]; }
    __syncthreads();
    __half* dst = g_w1t16 + (size_t)e*H_*D_;
#pragma unroll
    for (int i=0;i<4;i++){ int r=r0+8*i; dst[(size_t)(h0+r)*D_ + d0 + c] = __float2half_rn(t[c][r]); }
}

__global__ void cvt_w2_kernel(const float* __restrict__ W2){   // [KBIG,D] -> [D,KBIG] fp16
    __shared__ float t[32][33];
    int k0 = blockIdx.x*32, d0 = blockIdx.y*32;
    int c = threadIdx.x, r0 = threadIdx.y;
#pragma unroll
    for (int i=0;i<4;i++){ int r=r0+8*i; t[r][c] = W2[(size_t)(k0+r)*D_ + d0 + c]; }
    __syncthreads();
#pragma unroll
    for (int i=0;i<4;i++){ int r=r0+8*i; g_w2t16[(size_t)(d0+r)*KBIG + k0 + c] = __float2half_rn(t[c][r]); }
}

// ------------------ stage loader ------------------
__device__ __forceinline__ void load_stage(const __half* __restrict__ A,
                                           const __half* __restrict__ B,
                                           int ldK, uint32_t sbase, int stage, int k0, int tid){
    uint32_t sb = sbase + stage*STAGE_BYTES;
    const __half* a = A + k0;
    const __half* b = B + k0;
#pragma unroll
    for (int i=0;i<4;i++){
        int idx = tid + i*128;
        int r = idx>>2, c = idx&3;
        cpa(sb + r*80 + c*16, a + (size_t)r*ldK + c*8);
    }
#pragma unroll
    for (int i=0;i<4;i++){
        int idx = tid + i*128;
        int r = idx>>2, c = idx&3;
        cpa(sb + OPB + r*80 + c*16, b + (size_t)r*ldK + c*8);
    }
}

// ------------------ fp16 HMMA GEMM ------------------
// MODE 0: hidden = relu(x@W1T[e]+b1)*gate -> g_hs16      (K = D_)
// MODE 1: out = hs@W2T + sum_e gate*b2                   (K = KBIG)
template<int MODE>
__global__ __launch_bounds__(128, 2)
void gemm_f16(const float* __restrict__ bias, float* __restrict__ outp){
    extern __shared__ char smem[];
    uint32_t sbase = smem_u32(smem);
    int tid = threadIdx.x;
    int lane = tid & 31, warp = tid >> 5;
    int wm = warp & 1, wn = warp >> 1;          // 2x2 warp grid, 64x64 warp tile

    int n0 = blockIdx.y * BM;                   // token rows
    int c0 = blockIdx.x * BN;                   // output cols

    const __half *Ag, *Bg;
    int K;
    if (MODE == 0){
        Ag = g_x16 + (size_t)n0 * D_;
        Bg = g_w1t16 + (size_t)blockIdx.z*H_*D_ + (size_t)c0 * D_;
        K = D_;
    } else {
        Ag = g_hs16 + (size_t)n0 * KBIG;
        Bg = g_w2t16 + (size_t)c0 * KBIG;
        K = KBIG;
    }
    const int NC = K / BKH;

    float acc[4][8][4];
#pragma unroll
    for (int i=0;i<4;i++)
#pragma unroll
        for (int j=0;j<8;j++)
#pragma unroll
            for (int q=0;q<4;q++) acc[i][j][q] = 0.f;

    // ldmatrix lane offsets (within stage)
    uint32_t aoff = (uint32_t)((wm*64 + (lane&15))*80 + (lane>>4)*16);
    uint32_t boff = (uint32_t)(OPB + (wn*64 + ((lane>>4)<<3) + (lane&7))*80 + ((lane>>3)&1)*16);

    // prologue: stages 0..2
#pragma unroll
    for (int s=0;s<3;s++){
        load_stage(Ag, Bg, K, sbase, s, s*BKH, tid);
        asm volatile("cp.async.commit_group;");
    }

    for (int kt=0; kt<NC; kt++){
        if (kt+3 < NC) load_stage(Ag, Bg, K, sbase, (kt+3)&3, (kt+3)*BKH, tid);
        asm volatile("cp.async.commit_group;");
        asm volatile("cp.async.wait_group 3;");
        __syncthreads();

        uint32_t st = sbase + (uint32_t)(kt&3)*STAGE_BYTES;
#pragma unroll
        for (int ks=0; ks<2; ks++){
            uint32_t af[4][4], bf[4][4];
#pragma unroll
            for (int mi=0; mi<4; mi++)
                ldsm4(af[mi], st + aoff + mi*(16*80) + ks*32);
#pragma unroll
            for (int np=0; np<4; np++)
                ldsm4(bf[np], st + boff + np*(16*80) + ks*32);
#pragma unroll
            for (int mi=0; mi<4; mi++)
#pragma unroll
                for (int ni=0; ni<8; ni++)
                    mma16816(acc[mi][ni], af[mi], &bf[ni>>1][(ni&1)*2]);
        }
        __syncthreads();
    }
    asm volatile("cp.async.wait_group 0;");
    __syncthreads();

    if (MODE == 0){
        int e = blockIdx.z;
        float* bsm = (float*)smem;
        bsm[tid] = bias[(size_t)e*H_ + c0 + tid];     // 128 threads, 128 cols
        __syncthreads();
#pragma unroll
        for (int mi=0; mi<4; mi++){
#pragma unroll
            for (int h=0; h<2; h++){
                int tok = n0 + wm*64 + mi*16 + (lane>>2) + h*8;
                float gt = g_gate[tok*E_ + e];
                __half* dst = g_hs16 + (size_t)tok*KBIG + (size_t)e*H_ + c0;
#pragma unroll
                for (int ni=0; ni<8; ni++){
                    int col = wn*64 + ni*8 + (lane&3)*2;
                    float v0 = fmaxf(acc[mi][ni][h*2+0] + bsm[col],   0.f) * gt;
                    float v1 = fmaxf(acc[mi][ni][h*2+1] + bsm[col+1], 0.f) * gt;
                    *(__half2*)(dst + col) = __halves2half2(__float2half_rn(v0), __float2half_rn(v1));
                }
            }
        }
    } else {
        float* bsm = (float*)smem;                    // [8][128]
        for (int i = tid; i < E_*BN; i += 128){
            int e = i >> 7, c = i & 127;
            bsm[i] = bias[(size_t)e*D_ + c0 + c];
        }
        __syncthreads();
#pragma unroll
        for (int mi=0; mi<4; mi++){
#pragma unroll
            for (int h=0; h<2; h++){
                int tok = n0 + wm*64 + mi*16 + (lane>>2) + h*8;
                const float4* gp = (const float4*)(g_gate + (size_t)tok*E_);
                float4 ga = gp[0], gb = gp[1];
                float gt[8] = {ga.x,ga.y,ga.z,ga.w,gb.x,gb.y,gb.z,gb.w};
                float* dst = outp + (size_t)tok*D_ + c0;
#pragma unroll
                for (int ni=0; ni<8; ni++){
                    int col = wn*64 + ni*8 + (lane&3)*2;
                    float v0 = acc[mi][ni][h*2+0];
                    float v1 = acc[mi][ni][h*2+1];
#pragma unroll
                    for (int e=0;e<E_;e++){
                        v0 = fmaf(gt[e], bsm[e*BN+col],   v0);
                        v1 = fmaf(gt[e], bsm[e*BN+col+1], v1);
                    }
                    float2 v = make_float2(v0, v1);
                    *(float2*)(dst + col) = v;
                }
            }
        }
    }
}

// ---------------------------------------------------------------------------
extern "C" void kernel_launch(void* const* d_in, const int* in_sizes, int n_in,
                              void* d_out, int out_size)
{
    const float* x  = (const float*)d_in[0];
    const float* Wg = (const float*)d_in[1];
    const float* bg = (const float*)d_in[2];
    const float* W1 = (const float*)d_in[3];
    const float* b1 = (const float*)d_in[4];
    const float* W2 = (const float*)d_in[5];
    const float* b2 = (const float*)d_in[6];
    float* out = (float*)d_out;

    cudaFuncSetAttribute(gemm_f16<0>, cudaFuncAttributeMaxDynamicSharedMemorySize, SMEM_BYTES);
    cudaFuncSetAttribute(gemm_f16<1>, cudaFuncAttributeMaxDynamicSharedMemorySize, SMEM_BYTES);

    gate_kernel<<<NTOK*32/256, 256>>>(x, Wg, bg);
    cvt_x_kernel<<<(NTOK*D_)/1024, 256>>>(x);
    cvt_w1_kernel<<<dim3(H_/32, D_/32, E_), dim3(32,8)>>>(W1);
    cvt_w2_kernel<<<dim3(KBIG/32, D_/32), dim3(32,8)>>>(W2);

    gemm_f16<0><<<dim3(H_/BN, NTOK/BM, E_), 128, SMEM_BYTES>>>(b1, nullptr);
    gemm_f16<1><<<dim3(D_/BN, NTOK/BM, 1), 128, SMEM_BYTES>>>(b2, out);
}

// round 4
// speedup vs baseline: 8.1396x; 1.2130x over previous
#include <cuda_runtime.h>
#include <cuda_fp16.h>
#include <stdint.h>

#define NTOK 8192
#define D_   1024
#define H_   2048
#define E_   8
#define KBIG (E_*H_)

#define BM 128
#define BN 128
#define BKH 64                    // halves of K per stage (128B rows)
#define OPB (128*128)             // bytes per operand per stage (128 rows x 128B)
#define STAGE_BYTES (2*OPB)       // 32768
#define NSTAGE 3
#define SMEM_BYTES (NSTAGE*STAGE_BYTES)   // 98304

// ------------------ scratch ------------------
__device__ float g_gate[NTOK*E_];
__device__ __half g_x16[(size_t)NTOK*D_];
__device__ __half g_w1t16[(size_t)E_*H_*D_];   // [E][H][D]
__device__ __half g_w2t16[(size_t)D_*KBIG];    // [D][KBIG]
__device__ __half g_hs16[(size_t)NTOK*KBIG];   // [NTOK][KBIG]

// ------------------ PTX helpers ------------------
__device__ __forceinline__ uint32_t smem_u32(const void* p){
    uint32_t a;
    asm("{ .reg .u64 t; cvta.to.shared.u64 t, %1; cvt.u32.u64 %0, t; }" : "=r"(a) : "l"(p));
    return a;
}
__device__ __forceinline__ void cpa(uint32_t dst, const void* src){
    asm volatile("cp.async.cg.shared.global [%0], [%1], 16;" :: "r"(dst), "l"(src));
}
__device__ __forceinline__ void ldsm4(uint32_t* r, uint32_t addr){
    asm volatile("ldmatrix.sync.aligned.m8n8.x4.shared.b16 {%0,%1,%2,%3}, [%4];"
        : "=r"(r[0]), "=r"(r[1]), "=r"(r[2]), "=r"(r[3]) : "r"(addr));
}
__device__ __forceinline__ void mma16816(float* c, const uint32_t* a, const uint32_t* b){
    asm volatile("mma.sync.aligned.m16n8k16.row.col.f32.f16.f16.f32 "
        "{%0,%1,%2,%3}, {%4,%5,%6,%7}, {%8,%9}, {%0,%1,%2,%3};"
        : "+f"(c[0]), "+f"(c[1]), "+f"(c[2]), "+f"(c[3])
        : "r"(a[0]), "r"(a[1]), "r"(a[2]), "r"(a[3]), "r"(b[0]), "r"(b[1]));
}

// ------------------ gate = softmax(x@Wg + bg) ------------------
__global__ void gate_kernel(const float* __restrict__ x, const float* __restrict__ Wg,
                            const float* __restrict__ bg){
    int gw = (blockIdx.x*blockDim.x + threadIdx.x) >> 5;
    int lane = threadIdx.x & 31;
    if (gw >= NTOK) return;
    const float* xr = x + (size_t)gw * D_;
    float acc[E_];
#pragma unroll
    for (int e=0;e<E_;e++) acc[e]=0.f;
    for (int k=lane;k<D_;k+=32){
        float xv = xr[k];
        float4 w0 = *(const float4*)(Wg + k*E_);
        float4 w1 = *(const float4*)(Wg + k*E_ + 4);
        acc[0]=fmaf(xv,w0.x,acc[0]); acc[1]=fmaf(xv,w0.y,acc[1]);
        acc[2]=fmaf(xv,w0.z,acc[2]); acc[3]=fmaf(xv,w0.w,acc[3]);
        acc[4]=fmaf(xv,w1.x,acc[4]); acc[5]=fmaf(xv,w1.y,acc[5]);
        acc[6]=fmaf(xv,w1.z,acc[6]); acc[7]=fmaf(xv,w1.w,acc[7]);
    }
#pragma unroll
    for (int e=0;e<E_;e++)
#pragma unroll
        for (int o=16;o;o>>=1) acc[e] += __shfl_xor_sync(0xFFFFFFFFu, acc[e], o);
    if (lane==0){
        float m=-1e30f;
#pragma unroll
        for (int e=0;e<E_;e++){ acc[e]+=bg[e]; m=fmaxf(m,acc[e]); }
        float s=0.f;
#pragma unroll
        for (int e=0;e<E_;e++){ acc[e]=__expf(acc[e]-m); s+=acc[e]; }
        float inv=1.f/s;
#pragma unroll
        for (int e=0;e<E_;e++) g_gate[gw*E_+e]=acc[e]*inv;
    }
}

// ------------------ converts ------------------
__global__ void cvt_x_kernel(const float* __restrict__ x){
    size_t i = ((size_t)blockIdx.x*256 + threadIdx.x) * 4;
    float4 v = *(const float4*)(x + i);
    *(__half2*)(g_x16 + i)     = __halves2half2(__float2half_rn(v.x), __float2half_rn(v.y));
    *(__half2*)(g_x16 + i + 2) = __halves2half2(__float2half_rn(v.z), __float2half_rn(v.w));
}

// transpose [D,H]->[H,D] (per expert), half2 stores
__global__ void cvt_w1_kernel(const float* __restrict__ W1){
    __shared__ float t[32][33];
    int e = blockIdx.z;
    int h0 = blockIdx.x*32, d0 = blockIdx.y*32;
    int tid = threadIdx.x;                       // 256
    const float* src = W1 + (size_t)e*D_*H_;
#pragma unroll
    for (int i=0;i<4;i++){
        int idx = tid + i*256;                   // 1024
        int r = idx>>5, c = idx&31;              // r=d row, c=h col
        t[r][c] = src[(size_t)(d0+r)*H_ + h0 + c];
    }
    __syncthreads();
    __half* dst = g_w1t16 + (size_t)e*H_*D_;
#pragma unroll
    for (int i=0;i<2;i++){
        int u = tid + i*256;                     // 512 half2 units
        int h = u>>4, dp = u&15;
        __half2 v = __halves2half2(__float2half_rn(t[2*dp][h]), __float2half_rn(t[2*dp+1][h]));
        *(__half2*)(dst + (size_t)(h0+h)*D_ + d0 + 2*dp) = v;
    }
}

__global__ void cvt_w2_kernel(const float* __restrict__ W2){  // [KBIG,D]->[D,KBIG]
    __shared__ float t[32][33];
    int k0 = blockIdx.x*32, d0 = blockIdx.y*32;
    int tid = threadIdx.x;
#pragma unroll
    for (int i=0;i<4;i++){
        int idx = tid + i*256;
        int r = idx>>5, c = idx&31;              // r=k row, c=d col
        t[r][c] = W2[(size_t)(k0+r)*D_ + d0 + c];
    }
    __syncthreads();
#pragma unroll
    for (int i=0;i<2;i++){
        int u = tid + i*256;
        int d = u>>4, kp = u&15;
        __half2 v = __halves2half2(__float2half_rn(t[2*kp][d]), __float2half_rn(t[2*kp+1][d]));
        *(__half2*)(g_w2t16 + (size_t)(d0+d)*KBIG + k0 + 2*kp) = v;
    }
}

// ------------------ stage loader: 128 rows x 128B per operand, XOR swizzle ------------------
__device__ __forceinline__ void load_stage(const __half* __restrict__ A,
                                           const __half* __restrict__ B,
                                           int ldK, uint32_t sb, int k0, int tid){
#pragma unroll
    for (int i=0;i<8;i++){
        int idx = tid + i*128;
        int r = idx>>3, c = idx&7;
        uint32_t off = (uint32_t)(r*128 + ((c*16) ^ ((r&7)<<4)));
        cpa(sb + off, A + (size_t)r*ldK + k0 + c*8);
    }
#pragma unroll
    for (int i=0;i<8;i++){
        int idx = tid + i*128;
        int r = idx>>3, c = idx&7;
        uint32_t off = (uint32_t)(r*128 + ((c*16) ^ ((r&7)<<4)));
        cpa(sb + OPB + off, B + (size_t)r*ldK + k0 + c*8);
    }
}

// ------------------ fp16 HMMA GEMM ------------------
// MODE 0: hs = relu(x@W1T[e]+b1)*gate   (K=D_);  MODE 1: out = hs@W2T + sum_e gate*b2  (K=KBIG)
template<int MODE>
__global__ __launch_bounds__(128, 2)
void gemm_f16(const float* __restrict__ bias, float* __restrict__ outp){
    extern __shared__ char smem[];
    uint32_t sbase = smem_u32(smem);
    int tid = threadIdx.x;
    int lane = tid & 31, warp = tid >> 5;
    int wm = warp & 1, wn = warp >> 1;

    int n0 = blockIdx.y * BM;
    int c0 = blockIdx.x * BN;

    const __half *Ag, *Bg;
    int K;
    if (MODE == 0){
        Ag = g_x16 + (size_t)n0 * D_;
        Bg = g_w1t16 + (size_t)blockIdx.z*H_*D_ + (size_t)c0 * D_;
        K = D_;
    } else {
        Ag = g_hs16 + (size_t)n0 * KBIG;
        Bg = g_w2t16 + (size_t)c0 * KBIG;
        K = KBIG;
    }
    const int NC = K / BKH;

    float acc[4][8][4];
#pragma unroll
    for (int i=0;i<4;i++)
#pragma unroll
        for (int j=0;j<8;j++)
#pragma unroll
            for (int q=0;q<4;q++) acc[i][j][q] = 0.f;

    // per-thread ldmatrix geometry (rows fixed; swizzle XOR constant across 16-row steps)
    int arow = wm*64 + (lane&15);
    uint32_t axor = (uint32_t)((arow&7)<<4);
    uint32_t abase = (uint32_t)(arow*128) + ((uint32_t)((lane>>4)*16) ^ axor);
    int brow = wn*64 + ((lane>>4)<<3) + (lane&7);
    uint32_t bxor = (uint32_t)((brow&7)<<4);
    uint32_t bbase = (uint32_t)(OPB + brow*128) + ((uint32_t)(((lane>>3)&1)*16) ^ bxor);
    // note: ks column term must be XORed with the same row-xor; since ks*32 only touches
    // bits >=5 and xor is bits 4-6, ks*32 ^ xor == ks*32 + adjustments... careful: xor bits 0x70
    // overlap ks*32 (0x20,0x40). So compute full column each time: (colbytes ^ xor).

    // prologue: stages 0,1
    load_stage(Ag, Bg, K, sbase + 0*STAGE_BYTES, 0*BKH, tid);
    asm volatile("cp.async.commit_group;");
    load_stage(Ag, Bg, K, sbase + 1*STAGE_BYTES, 1*BKH, tid);
    asm volatile("cp.async.commit_group;");

    int sidx = 0;                          // stage of chunk kt
    for (int kt=0; kt<NC; kt++){
        asm volatile("cp.async.wait_group 1;");
        __syncthreads();

        // issue loads for kt+2 into freed stage
        int snext = sidx + 2; if (snext >= NSTAGE) snext -= NSTAGE;
        if (kt+2 < NC)
            load_stage(Ag, Bg, K, sbase + snext*STAGE_BYTES, (kt+2)*BKH, tid);
        asm volatile("cp.async.commit_group;");

        uint32_t st = sbase + (uint32_t)sidx*STAGE_BYTES;
        uint32_t arow0 = st + (uint32_t)(arow*128);
        uint32_t brow0 = st + (uint32_t)(OPB + brow*128);
        uint32_t acol0 = (uint32_t)((lane>>4)*16);
        uint32_t bcol0 = (uint32_t)(((lane>>3)&1)*16);

        uint32_t af[2][4][4], bf[2][4][4];
        // preload ks=0
#pragma unroll
        for (int mi=0; mi<4; mi++) ldsm4(af[0][mi], arow0 + mi*(16*128) + ((acol0) ^ axor));
#pragma unroll
        for (int np=0; np<4; np++) ldsm4(bf[0][np], brow0 + np*(16*128) + ((bcol0) ^ bxor));

#pragma unroll
        for (int ks=0; ks<4; ks++){
            int cur = ks & 1, nxt = cur ^ 1;
            if (ks < 3){
                uint32_t ac = (uint32_t)((ks+1)*32) + acol0;
                uint32_t bc = (uint32_t)((ks+1)*32) + bcol0;
#pragma unroll
                for (int mi=0; mi<4; mi++) ldsm4(af[nxt][mi], arow0 + mi*(16*128) + (ac ^ axor));
#pragma unroll
                for (int np=0; np<4; np++) ldsm4(bf[nxt][np], brow0 + np*(16*128) + (bc ^ bxor));
            }
#pragma unroll
            for (int mi=0; mi<4; mi++)
#pragma unroll
                for (int ni=0; ni<8; ni++)
                    mma16816(acc[mi][ni], af[cur][mi], &bf[cur][ni>>1][(ni&1)*2]);
        }
        sidx = snext - 1; if (sidx < 0) sidx += NSTAGE;   // sidx = (kt+1)%NSTAGE
    }
    asm volatile("cp.async.wait_group 0;");
    __syncthreads();

    if (MODE == 0){
        int e = blockIdx.z;
        float* bsm = (float*)smem;
        bsm[tid] = bias[(size_t)e*H_ + c0 + tid];
        __syncthreads();
#pragma unroll
        for (int mi=0; mi<4; mi++){
#pragma unroll
            for (int h=0; h<2; h++){
                int tok = n0 + wm*64 + mi*16 + (lane>>2) + h*8;
                float gt = g_gate[tok*E_ + e];
                __half* dst = g_hs16 + (size_t)tok*KBIG + (size_t)e*H_ + c0;
#pragma unroll
                for (int ni=0; ni<8; ni++){
                    int col = wn*64 + ni*8 + (lane&3)*2;
                    float v0 = fmaxf(acc[mi][ni][h*2+0] + bsm[col],   0.f) * gt;
                    float v1 = fmaxf(acc[mi][ni][h*2+1] + bsm[col+1], 0.f) * gt;
                    *(__half2*)(dst + col) = __halves2half2(__float2half_rn(v0), __float2half_rn(v1));
                }
            }
        }
    } else {
        float* bsm = (float*)smem;       // [8][128]
        for (int i = tid; i < E_*BN; i += 128){
            int e = i >> 7, c = i & 127;
            bsm[i] = bias[(size_t)e*D_ + c0 + c];
        }
        __syncthreads();
#pragma unroll
        for (int mi=0; mi<4; mi++){
#pragma unroll
            for (int h=0; h<2; h++){
                int tok = n0 + wm*64 + mi*16 + (lane>>2) + h*8;
                const float4* gp = (const float4*)(g_gate + (size_t)tok*E_);
                float4 ga = gp[0], gb = gp[1];
                float gt[8] = {ga.x,ga.y,ga.z,ga.w,gb.x,gb.y,gb.z,gb.w};
                float* dst = outp + (size_t)tok*D_ + c0;
#pragma unroll
                for (int ni=0; ni<8; ni++){
                    int col = wn*64 + ni*8 + (lane&3)*2;
                    float v0 = acc[mi][ni][h*2+0];
                    float v1 = acc[mi][ni][h*2+1];
#pragma unroll
                    for (int e=0;e<E_;e++){
                        v0 = fmaf(gt[e], bsm[e*BN+col],   v0);
                        v1 = fmaf(gt[e], bsm[e*BN+col+1], v1);
                    }
                    *(float2*)(dst + col) = make_float2(v0, v1);
                }
            }
        }
    }
}

// ---------------------------------------------------------------------------
extern "C" void kernel_launch(void* const* d_in, const int* in_sizes, int n_in,
                              void* d_out, int out_size)
{
    const float* x  = (const float*)d_in[0];
    const float* Wg = (const float*)d_in[1];
    const float* bg = (const float*)d_in[2];
    const float* W1 = (const float*)d_in[3];
    const float* b1 = (const float*)d_in[4];
    const float* W2 = (const float*)d_in[5];
    const float* b2 = (const float*)d_in[6];
    float* out = (float*)d_out;

    cudaFuncSetAttribute(gemm_f16<0>, cudaFuncAttributeMaxDynamicSharedMemorySize, SMEM_BYTES);
    cudaFuncSetAttribute(gemm_f16<1>, cudaFuncAttributeMaxDynamicSharedMemorySize, SMEM_BYTES);

    gate_kernel<<<NTOK*32/256, 256>>>(x, Wg, bg);
    cvt_x_kernel<<<(NTOK*D_)/1024, 256>>>(x);
    cvt_w1_kernel<<<dim3(H_/32, D_/32, E_), 256>>>(W1);
    cvt_w2_kernel<<<dim3(KBIG/32, D_/32), 256>>>(W2);

    gemm_f16<0><<<dim3(H_/BN, NTOK/BM, E_), 128, SMEM_BYTES>>>(b1, nullptr);
    gemm_f16<1><<<dim3(D_/BN, NTOK/BM, 1), 128, SMEM_BYTES>>>(b2, out);
}